// round 13
// baseline (speedup 1.0000x reference)
#include <cuda_runtime.h>
#include <cstdint>

#define N_NODES   100000
#define N_EDGES   1600000
#define FEAT_DIM  128
#define EMBED_DIM 32
#define NC        17
#define A_STRIDE  32   // 128B rows
#define FT_PAD    257
#define KT        16
#define P_PAD     33
#define B_PAD     21
#define NTOPB     512  // scan-top width (>= 391)

// -------- device scratch ----------------------------------------------------
__device__ __align__(16) float g_embed[N_NODES * EMBED_DIM];
__device__ __align__(16) float g_A[N_NODES * A_STRIDE];
__device__ int g_cnt[N_NODES];
__device__ int g_off[N_NODES];
__device__ int g_cur[N_NODES];
__device__ int g_bsum[NTOPB];
__device__ int g_eids[N_EDGES];

// -------- f32x2 helpers -----------------------------------------------------
__device__ __forceinline__ unsigned long long pk2(float lo, float hi) {
    unsigned long long r;
    asm("mov.b64 %0, {%1,%2};" : "=l"(r) : "f"(lo), "f"(hi));
    return r;
}
__device__ __forceinline__ void upk2(unsigned long long v, float& lo, float& hi) {
    asm("mov.b64 {%0,%1}, %2;" : "=f"(lo), "=f"(hi) : "l"(v));
}
__device__ __forceinline__ unsigned long long fma2(unsigned long long a,
                                                   unsigned long long b,
                                                   unsigned long long c) {
    unsigned long long d;
    asm("fma.rn.f32x2 %0, %1, %2, %3;" : "=l"(d) : "l"(a), "l"(b), "l"(c));
    return d;
}

// ============================================================================
// Kernel A (R6 version): one node per thread, W broadcast, fused A epilogue.
// ============================================================================
__global__ __launch_bounds__(256) void node_kernel(
    const float* __restrict__ feat, const float* __restrict__ Wemb,
    const float* __restrict__ bemb, const float* __restrict__ Wtr)
{
    __shared__ __align__(16) float sFeatT[KT * FT_PAD];
    __shared__ __align__(16) float sW[FEAT_DIM * EMBED_DIM];
    __shared__ __align__(16) unsigned long long sW1h2[EMBED_DIM][9];
    __shared__ __align__(16) unsigned long long sW22[EMBED_DIM][9];
    __shared__ __align__(16) unsigned long long sB2[16];

    const int t = threadIdx.x;
    {
        const float4* W4  = (const float4*)Wemb;
        float4*       sW4 = (float4*)sW;
        #pragma unroll
        for (int i = t; i < FEAT_DIM * EMBED_DIM / 4; i += 256) sW4[i] = W4[i];
        for (int i = t; i < EMBED_DIM * 9; i += 256) {
            int k = i / 9, c2 = i % 9, c = 2 * c2;
            float l1 = (c     < NC) ? 0.5f * Wtr[k * NC + c]     : 0.f;
            float h1 = (c + 1 < NC) ? 0.5f * Wtr[k * NC + c + 1] : 0.f;
            float l2 = (c     < NC) ? Wtr[(EMBED_DIM + k) * NC + c]     : 0.f;
            float h2 = (c + 1 < NC) ? Wtr[(EMBED_DIM + k) * NC + c + 1] : 0.f;
            sW1h2[k][c2] = pk2(l1, h1);
            sW22[k][c2]  = pk2(l2, h2);
        }
        if (t < 16) sB2[t] = pk2(bemb[2 * t], bemb[2 * t + 1]);
    }
    __syncthreads();

    const int n0 = blockIdx.x * 256;
    const int n  = n0 + t;

    unsigned long long acc2[16];
    #pragma unroll
    for (int j2 = 0; j2 < 16; j2++) acc2[j2] = sB2[j2];

    for (int kt = 0; kt < FEAT_DIM / KT; kt++) {
        if (kt) __syncthreads();
        const int kk = (t & 3) * 4;
        #pragma unroll
        for (int pass = 0; pass < 4; pass++) {
            int col = pass * 64 + (t >> 2);
            int nn  = n0 + col; if (nn >= N_NODES) nn = N_NODES - 1;
            float4 f = __ldg((const float4*)(feat + (size_t)nn * FEAT_DIM + kt * KT + kk));
            sFeatT[(kk + 0) * FT_PAD + col] = f.x;
            sFeatT[(kk + 1) * FT_PAD + col] = f.y;
            sFeatT[(kk + 2) * FT_PAD + col] = f.z;
            sFeatT[(kk + 3) * FT_PAD + col] = f.w;
        }
        __syncthreads();

        #pragma unroll
        for (int k = 0; k < KT; k++) {
            float e = sFeatT[k * FT_PAD + t];
            unsigned long long e2 = pk2(e, e);
            const ulonglong2* wr = (const ulonglong2*)&sW[(kt * KT + k) * EMBED_DIM];
            #pragma unroll
            for (int j4 = 0; j4 < 8; j4++) {
                ulonglong2 w = wr[j4];
                acc2[2 * j4    ] = fma2(e2, w.x, acc2[2 * j4    ]);
                acc2[2 * j4 + 1] = fma2(e2, w.y, acc2[2 * j4 + 1]);
            }
        }
    }

    unsigned long long accA[9];
    #pragma unroll
    for (int c2 = 0; c2 < 9; c2++) accA[c2] = 0ull;
    #pragma unroll
    for (int k2 = 0; k2 < 16; k2++) {
        float e0, e1; upk2(acc2[k2], e0, e1);
        unsigned long long ea = pk2(e0, e0), eb = pk2(e1, e1);
        #pragma unroll
        for (int c2 = 0; c2 < 9; c2++) {
            unsigned long long t0 = fma2(ea, sW22[2 * k2][c2],     sW1h2[2 * k2][c2]);
            accA[c2] = fma2(ea, t0, accA[c2]);
            unsigned long long t1 = fma2(eb, sW22[2 * k2 + 1][c2], sW1h2[2 * k2 + 1][c2]);
            accA[c2] = fma2(eb, t1, accA[c2]);
        }
    }

    if (n < N_NODES) {
        ulonglong2* eo = (ulonglong2*)(g_embed + (size_t)n * EMBED_DIM);
        #pragma unroll
        for (int i = 0; i < 8; i++)
            eo[i] = make_ulonglong2(acc2[2 * i], acc2[2 * i + 1]);
        unsigned long long* Ao = (unsigned long long*)(g_A + (size_t)n * A_STRIDE);
        #pragma unroll
        for (int c2 = 0; c2 < 8; c2++) Ao[c2] = accA[c2];
        float lo, hi; upk2(accA[8], lo, hi);
        ((float*)Ao)[16] = lo;
    }
}

// ============================================================================
// Kernel B: gather + logits + softmax + poss_edge writeout. NO atomics.
// ============================================================================
__global__ __launch_bounds__(256) void edge_kernel(
    const int2* __restrict__ edges,
    const float* __restrict__ Wtr, const float* __restrict__ btr,
    float* __restrict__ out_pe)
{
    __shared__ __align__(16) unsigned long long sW2p[NC][16];
    __shared__ float sB[NC];
    __shared__ float sP[8][32 * P_PAD];
    __shared__ float sBase[8][32 * B_PAD];

    const int t    = threadIdx.x;
    const int w    = t >> 5;
    const int lane = t & 31;

    for (int i = t; i < NC * 16; i += 256) {
        int c = i >> 4, k2 = i & 15;
        float lo = -2.f * Wtr[(EMBED_DIM + 2 * k2    ) * NC + c];
        float hi = -2.f * Wtr[(EMBED_DIM + 2 * k2 + 1) * NC + c];
        sW2p[c][k2] = pk2(lo, hi);
    }
    if (t < NC) sB[t] = btr[t];
    __syncthreads();

    float* myP    = sP[w];
    float* myBase = sBase[w];
    const int wb  = w * 32;

    // cooperative gather: 8 lanes per row
    {
        const int sub = lane >> 3;
        const int k4  = lane & 7;
        #pragma unroll
        for (int i = 0; i < 8; i++) {
            const int e  = i * 4 + sub;
            const int ge = blockIdx.x * 256 + wb + e;
            const int2 ed = __ldg(&edges[ge]);
            const int srow = ed.x, drow = ed.y;
            float4 a = __ldg((const float4*)(g_embed + (size_t)srow * EMBED_DIM) + k4);
            float4 b = __ldg((const float4*)(g_embed + (size_t)drow * EMBED_DIM) + k4);
            float* pp = myP + e * P_PAD + 4 * k4;
            pp[0] = a.x * b.x; pp[1] = a.y * b.y; pp[2] = a.z * b.z; pp[3] = a.w * b.w;
            if (k4 < 5) {
                float4 c4 = __ldg((const float4*)(g_A + (size_t)srow * A_STRIDE) + k4);
                float4 d4 = __ldg((const float4*)(g_A + (size_t)drow * A_STRIDE) + k4);
                float* bb = myBase + e * B_PAD + 4 * k4;
                bb[0] = c4.x + d4.x; bb[1] = c4.y + d4.y;
                bb[2] = c4.z + d4.z;
                if (k4 < 4) bb[3] = c4.w + d4.w;
            }
        }
    }
    __syncwarp();

    float logit[NC];
    {
        unsigned long long p2[16];
        const float* pr = myP + lane * P_PAD;
        #pragma unroll
        for (int k2 = 0; k2 < 16; k2++) p2[k2] = pk2(pr[2 * k2], pr[2 * k2 + 1]);
        const float* br = myBase + lane * B_PAD;
        #pragma unroll
        for (int c = 0; c < NC; c++) {
            unsigned long long acc = 0ull;
            #pragma unroll
            for (int k2 = 0; k2 < 16; k2++)
                acc = fma2(p2[k2], sW2p[c][k2], acc);
            float lo, hi; upk2(acc, lo, hi);
            logit[c] = sB[c] + br[c] + lo + hi;
        }
    }

    float m = logit[0];
    #pragma unroll
    for (int c = 1; c < NC; c++) m = fmaxf(m, logit[c]);
    float sum = 0.f;
    #pragma unroll
    for (int c = 0; c < NC; c++) { logit[c] = __expf(logit[c] - m); sum += logit[c]; }
    const float inv = __fdividef(1.f, sum);
    #pragma unroll
    for (int c = 0; c < NC; c++) logit[c] *= inv;

    {
        float* br = myBase + lane * B_PAD;
        #pragma unroll
        for (int c = 0; c < NC; c++) br[c] = logit[c];
    }
    __syncwarp();

    // coalesced poss_edge writeout (keep cacheable: recall kernel re-reads it)
    float* outw = out_pe + (size_t)(blockIdx.x * 256 + wb) * NC;
    #pragma unroll
    for (int j = 0; j < NC; j++) {
        const int idx = j * 32 + lane;
        const int e   = idx / NC;
        const int c   = idx - e * NC;
        outw[idx] = myBase[e * B_PAD + c];
    }
}

// ============================================================================
// CSR build
// ============================================================================
__global__ __launch_bounds__(256) void zero_cnt_kernel()
{
    for (int i = blockIdx.x * 256 + threadIdx.x; i < N_NODES; i += gridDim.x * 256)
        g_cnt[i] = 0;
}

__global__ __launch_bounds__(256) void hist_kernel(const int2* __restrict__ edges)
{
    const int e = blockIdx.x * 256 + threadIdx.x;
    if (e < N_EDGES) atomicAdd(&g_cnt[edges[e].x], 1);
}

__global__ __launch_bounds__(256) void scan_part_kernel()   // 391 blocks
{
    __shared__ int sd[256];
    const int i = blockIdx.x * 256 + threadIdx.x;
    int v = (i < N_NODES) ? g_cnt[i] : 0;
    sd[threadIdx.x] = v;
    __syncthreads();
    for (int o = 128; o > 0; o >>= 1) {
        if (threadIdx.x < o) sd[threadIdx.x] += sd[threadIdx.x + o];
        __syncthreads();
    }
    if (threadIdx.x == 0) g_bsum[blockIdx.x] = sd[0];
}

__global__ __launch_bounds__(NTOPB) void scan_top_kernel(int nblocks)  // 1 block
{
    __shared__ int sd[NTOPB];
    const int t = threadIdx.x;
    int v = (t < nblocks) ? g_bsum[t] : 0;
    sd[t] = v;
    __syncthreads();
    for (int o = 1; o < NTOPB; o <<= 1) {
        int add = (t >= o) ? sd[t - o] : 0;
        __syncthreads();
        sd[t] += add;
        __syncthreads();
    }
    g_bsum[t] = sd[t] - v;   // exclusive
}

__global__ __launch_bounds__(256) void scan_final_kernel()  // 391 blocks
{
    __shared__ int sd[256];
    const int i = blockIdx.x * 256 + threadIdx.x;
    const int t = threadIdx.x;
    int v = (i < N_NODES) ? g_cnt[i] : 0;
    sd[t] = v;
    __syncthreads();
    for (int o = 1; o < 256; o <<= 1) {
        int add = (t >= o) ? sd[t - o] : 0;
        __syncthreads();
        sd[t] += add;
        __syncthreads();
    }
    if (i < N_NODES) {
        int off = g_bsum[blockIdx.x] + sd[t] - v;   // exclusive
        g_off[i] = off;
        g_cur[i] = off;
    }
}

__global__ __launch_bounds__(256) void scatter_kernel(const int2* __restrict__ edges)
{
    const int e = blockIdx.x * 256 + threadIdx.x;
    if (e < N_EDGES) {
        int pos = atomicAdd(&g_cur[edges[e].x], 1);
        g_eids[pos] = e;
    }
}

// ============================================================================
// Kernel R: per-node recall via CSR — no atomics. One warp per node.
// lanes 0..16 = classes; edge ids broadcast-loaded.
// ============================================================================
__global__ __launch_bounds__(256) void recall_kernel(
    const float* __restrict__ pe, const float* __restrict__ weights,
    const float* __restrict__ ns,
    float* __restrict__ out_pn, float* __restrict__ out_rn)
{
    const int w    = threadIdx.x >> 5;
    const int lane = threadIdx.x & 31;
    const int n    = blockIdx.x * 8 + w;
    if (n >= N_NODES) return;

    const int base = g_off[n];
    const int deg  = g_cnt[n];

    float acc = 0.f;
    int i = 0;
    for (; i + 2 <= deg; i += 2) {
        const int e0 = __ldg(&g_eids[base + i]);
        const int e1 = __ldg(&g_eids[base + i + 1]);
        const float w0 = __ldg(&weights[e0]);
        const float w1 = __ldg(&weights[e1]);
        if (lane < NC) {
            acc += __ldg(&pe[(size_t)e0 * NC + lane]) * w0;
            acc += __ldg(&pe[(size_t)e1 * NC + lane]) * w1;
        }
    }
    if (i < deg) {
        const int e0 = __ldg(&g_eids[base + i]);
        const float w0 = __ldg(&weights[e0]);
        if (lane < NC) acc += __ldg(&pe[(size_t)e0 * NC + lane]) * w0;
    }

    if (lane < NC) {
        out_rn[(size_t)n * NC + lane] = acc;
        out_pn[(size_t)n * NC + lane] = acc / __ldg(&ns[n]);
    }
}

// ============================================================================
extern "C" void kernel_launch(void* const* d_in, const int* in_sizes, int n_in,
                              void* d_out, int out_size)
{
    const void *p_feat = nullptr, *p_edges = nullptr, *p_w = nullptr,
               *p_ns = nullptr, *p_We = nullptr, *p_be = nullptr,
               *p_Wt = nullptr, *p_bt = nullptr;
    for (int i = 0; i < n_in; i++) {
        switch (in_sizes[i]) {
            case N_NODES * FEAT_DIM:      p_feat  = d_in[i]; break;
            case N_EDGES * 2:             p_edges = d_in[i]; break;
            case N_EDGES:                 p_w     = d_in[i]; break;
            case N_NODES:                 p_ns    = d_in[i]; break;
            case FEAT_DIM * EMBED_DIM:    p_We    = d_in[i]; break;
            case EMBED_DIM:               p_be    = d_in[i]; break;
            case 2 * EMBED_DIM * NC:      p_Wt    = d_in[i]; break;
            case NC:                      p_bt    = d_in[i]; break;
            default: break;
        }
    }

    const float* feat    = (const float*)p_feat;
    const int2*  edges   = (const int2*)p_edges;
    const float* weights = (const float*)p_w;
    const float* ns      = (const float*)p_ns;
    const float* Wemb    = (const float*)p_We;
    const float* bemb    = (const float*)p_be;
    const float* Wtr     = (const float*)p_Wt;
    const float* btr     = (const float*)p_bt;

    float* out    = (float*)d_out;
    float* out_pn = out;
    float* out_pe = out + (size_t)N_NODES * NC;
    float* out_rn = out + (size_t)N_NODES * NC + (size_t)N_EDGES * NC;

    const int NB  = (N_NODES + 255) / 256;   // 391
    const int EB  = N_EDGES / 256;           // 6250

    zero_cnt_kernel<<<98, 256>>>();
    node_kernel<<<NB, 256>>>(feat, Wemb, bemb, Wtr);
    hist_kernel<<<EB, 256>>>(edges);
    scan_part_kernel<<<NB, 256>>>();
    scan_top_kernel<<<1, NTOPB>>>(NB);
    scan_final_kernel<<<NB, 256>>>();
    scatter_kernel<<<EB, 256>>>(edges);
    edge_kernel<<<EB, 256>>>(edges, Wtr, btr, out_pe);
    recall_kernel<<<(N_NODES + 7) / 8, 256>>>(out_pe, weights, ns, out_pn, out_rn);
}

// round 16
// speedup vs baseline: 1.3355x; 1.3355x over previous
#include <cuda_runtime.h>
#include <cstdint>

#define N_NODES   100000
#define N_EDGES   1600000
#define FEAT_DIM  128
#define EMBED_DIM 32
#define NC        17
#define A_STRIDE  32   // 128B rows
#define R_STRIDE  20   // 80B rows, 16B-aligned quads for red.v4
#define FT_PAD    257
#define KT        16
#define P_PAD     33   // sP row stride
#define B_PAD     21   // sBase row stride

// -------- device scratch ----------------------------------------------------
__device__ __align__(16) float g_embed[N_NODES * EMBED_DIM];
__device__ __align__(16) float g_A[N_NODES * A_STRIDE];     // cols 17..31 zero
__device__ __align__(16) float g_recall[N_NODES * R_STRIDE];

// -------- f32x2 helpers -----------------------------------------------------
__device__ __forceinline__ unsigned long long pk2(float lo, float hi) {
    unsigned long long r;
    asm("mov.b64 %0, {%1,%2};" : "=l"(r) : "f"(lo), "f"(hi));
    return r;
}
__device__ __forceinline__ void upk2(unsigned long long v, float& lo, float& hi) {
    asm("mov.b64 {%0,%1}, %2;" : "=f"(lo), "=f"(hi) : "l"(v));
}
__device__ __forceinline__ unsigned long long fma2(unsigned long long a,
                                                   unsigned long long b,
                                                   unsigned long long c) {
    unsigned long long d;
    asm("fma.rn.f32x2 %0, %1, %2, %3;" : "=l"(d) : "l"(a), "l"(b), "l"(c));
    return d;
}

// ============================================================================
// Kernel A (R6): one node per thread, W broadcast, fused A epilogue.
// ============================================================================
__global__ __launch_bounds__(256) void node_kernel(
    const float* __restrict__ feat, const float* __restrict__ Wemb,
    const float* __restrict__ bemb, const float* __restrict__ Wtr)
{
    __shared__ __align__(16) float sFeatT[KT * FT_PAD];
    __shared__ __align__(16) float sW[FEAT_DIM * EMBED_DIM];
    __shared__ __align__(16) unsigned long long sW1h2[EMBED_DIM][9];
    __shared__ __align__(16) unsigned long long sW22[EMBED_DIM][9];
    __shared__ __align__(16) unsigned long long sB2[16];

    const int t = threadIdx.x;
    {
        const float4* W4  = (const float4*)Wemb;
        float4*       sW4 = (float4*)sW;
        #pragma unroll
        for (int i = t; i < FEAT_DIM * EMBED_DIM / 4; i += 256) sW4[i] = W4[i];
        for (int i = t; i < EMBED_DIM * 9; i += 256) {
            int k = i / 9, c2 = i % 9, c = 2 * c2;
            float l1 = (c     < NC) ? 0.5f * Wtr[k * NC + c]     : 0.f;
            float h1 = (c + 1 < NC) ? 0.5f * Wtr[k * NC + c + 1] : 0.f;
            float l2 = (c     < NC) ? Wtr[(EMBED_DIM + k) * NC + c]     : 0.f;
            float h2 = (c + 1 < NC) ? Wtr[(EMBED_DIM + k) * NC + c + 1] : 0.f;
            sW1h2[k][c2] = pk2(l1, h1);
            sW22[k][c2]  = pk2(l2, h2);
        }
        if (t < 16) sB2[t] = pk2(bemb[2 * t], bemb[2 * t + 1]);
    }
    __syncthreads();

    const int n0 = blockIdx.x * 256;
    const int n  = n0 + t;

    unsigned long long acc2[16];
    #pragma unroll
    for (int j2 = 0; j2 < 16; j2++) acc2[j2] = sB2[j2];

    for (int kt = 0; kt < FEAT_DIM / KT; kt++) {
        if (kt) __syncthreads();
        const int kk = (t & 3) * 4;
        #pragma unroll
        for (int pass = 0; pass < 4; pass++) {
            int col = pass * 64 + (t >> 2);
            int nn  = n0 + col; if (nn >= N_NODES) nn = N_NODES - 1;
            float4 f = __ldg((const float4*)(feat + (size_t)nn * FEAT_DIM + kt * KT + kk));
            sFeatT[(kk + 0) * FT_PAD + col] = f.x;
            sFeatT[(kk + 1) * FT_PAD + col] = f.y;
            sFeatT[(kk + 2) * FT_PAD + col] = f.z;
            sFeatT[(kk + 3) * FT_PAD + col] = f.w;
        }
        __syncthreads();

        #pragma unroll
        for (int k = 0; k < KT; k++) {
            float e = sFeatT[k * FT_PAD + t];
            unsigned long long e2 = pk2(e, e);
            const ulonglong2* wr = (const ulonglong2*)&sW[(kt * KT + k) * EMBED_DIM];
            #pragma unroll
            for (int j4 = 0; j4 < 8; j4++) {
                ulonglong2 w = wr[j4];
                acc2[2 * j4    ] = fma2(e2, w.x, acc2[2 * j4    ]);
                acc2[2 * j4 + 1] = fma2(e2, w.y, acc2[2 * j4 + 1]);
            }
        }
    }

    unsigned long long accA[9];
    #pragma unroll
    for (int c2 = 0; c2 < 9; c2++) accA[c2] = 0ull;
    #pragma unroll
    for (int k2 = 0; k2 < 16; k2++) {
        float e0, e1; upk2(acc2[k2], e0, e1);
        unsigned long long ea = pk2(e0, e0), eb = pk2(e1, e1);
        #pragma unroll
        for (int c2 = 0; c2 < 9; c2++) {
            unsigned long long t0 = fma2(ea, sW22[2 * k2][c2],     sW1h2[2 * k2][c2]);
            accA[c2] = fma2(ea, t0, accA[c2]);
            unsigned long long t1 = fma2(eb, sW22[2 * k2 + 1][c2], sW1h2[2 * k2 + 1][c2]);
            accA[c2] = fma2(eb, t1, accA[c2]);
        }
    }

    if (n < N_NODES) {
        ulonglong2* eo = (ulonglong2*)(g_embed + (size_t)n * EMBED_DIM);
        #pragma unroll
        for (int i = 0; i < 8; i++)
            eo[i] = make_ulonglong2(acc2[2 * i], acc2[2 * i + 1]);
        unsigned long long* Ao = (unsigned long long*)(g_A + (size_t)n * A_STRIDE);
        #pragma unroll
        for (int c2 = 0; c2 < 8; c2++) Ao[c2] = accA[c2];
        float lo, hi; upk2(accA[8], lo, hi);
        ((float*)Ao)[16] = lo;
    }
}

// ============================================================================
// Kernel B (R6, unchanged): warp-cooperative gather + mixed vector RED.
// ============================================================================
__global__ __launch_bounds__(256) void edge_kernel(
    const int2* __restrict__ edges, const float* __restrict__ weights,
    const float* __restrict__ Wtr, const float* __restrict__ btr,
    float* __restrict__ out_pe)
{
    __shared__ __align__(16) unsigned long long sW2p[NC][16];
    __shared__ float sB[NC];
    __shared__ float sP[8][32 * P_PAD];
    __shared__ float sBase[8][32 * B_PAD];
    __shared__ int   sS[256];
    __shared__ float sWgt[256];

    const int t    = threadIdx.x;
    const int w    = t >> 5;
    const int lane = t & 31;

    for (int i = t; i < NC * 16; i += 256) {
        int c = i >> 4, k2 = i & 15;
        float lo = -2.f * Wtr[(EMBED_DIM + 2 * k2    ) * NC + c];
        float hi = -2.f * Wtr[(EMBED_DIM + 2 * k2 + 1) * NC + c];
        sW2p[c][k2] = pk2(lo, hi);
    }
    if (t < NC) sB[t] = btr[t];

    const int e_own = blockIdx.x * 256 + t;
    const int2 sd   = edges[e_own];
    sS[t]   = sd.x;
    sWgt[t] = weights[e_own];
    __syncthreads();

    float* myP    = sP[w];
    float* myBase = sBase[w];
    const int wb  = w * 32;

    {
        const int sub = lane >> 3;
        const int k4  = lane & 7;
        #pragma unroll
        for (int i = 0; i < 8; i++) {
            const int e  = i * 4 + sub;
            const int ge = blockIdx.x * 256 + wb + e;
            const int2 ed = __ldg(&edges[ge]);
            const int srow = ed.x, drow = ed.y;
            float4 a = __ldg((const float4*)(g_embed + (size_t)srow * EMBED_DIM) + k4);
            float4 b = __ldg((const float4*)(g_embed + (size_t)drow * EMBED_DIM) + k4);
            float* pp = myP + e * P_PAD + 4 * k4;
            pp[0] = a.x * b.x; pp[1] = a.y * b.y; pp[2] = a.z * b.z; pp[3] = a.w * b.w;
            if (k4 < 5) {
                float4 c4 = __ldg((const float4*)(g_A + (size_t)srow * A_STRIDE) + k4);
                float4 d4 = __ldg((const float4*)(g_A + (size_t)drow * A_STRIDE) + k4);
                float* bb = myBase + e * B_PAD + 4 * k4;
                bb[0] = c4.x + d4.x; bb[1] = c4.y + d4.y;
                bb[2] = c4.z + d4.z;
                if (k4 < 4) bb[3] = c4.w + d4.w;
            }
        }
    }
    __syncwarp();

    float logit[NC];
    {
        unsigned long long p2[16];
        const float* pr = myP + lane * P_PAD;
        #pragma unroll
        for (int k2 = 0; k2 < 16; k2++) p2[k2] = pk2(pr[2 * k2], pr[2 * k2 + 1]);
        const float* br = myBase + lane * B_PAD;
        #pragma unroll
        for (int c = 0; c < NC; c++) {
            unsigned long long acc = 0ull;
            #pragma unroll
            for (int k2 = 0; k2 < 16; k2++)
                acc = fma2(p2[k2], sW2p[c][k2], acc);
            float lo, hi; upk2(acc, lo, hi);
            logit[c] = sB[c] + br[c] + lo + hi;
        }
    }

    float m = logit[0];
    #pragma unroll
    for (int c = 1; c < NC; c++) m = fmaxf(m, logit[c]);
    float sum = 0.f;
    #pragma unroll
    for (int c = 0; c < NC; c++) { logit[c] = __expf(logit[c] - m); sum += logit[c]; }
    const float inv = __fdividef(1.f, sum);
    #pragma unroll
    for (int c = 0; c < NC; c++) logit[c] *= inv;

    {
        float* br = myBase + lane * B_PAD;
        #pragma unroll
        for (int c = 0; c < NC; c++) br[c] = logit[c];
    }
    __syncwarp();

    #pragma unroll
    for (int j = 0; j < 5; j++) {
        const int o = j * 32 + lane;
        const int e = o / 5;
        const int q = o - 5 * e;
        const float wg = sWgt[wb + e];
        const float* br = myBase + e * B_PAD;
        float* addr = g_recall + (size_t)sS[wb + e] * R_STRIDE + 4 * q;
        if (q < 4) {
            asm volatile("red.global.add.v4.f32 [%0], {%1,%2,%3,%4};" ::
                         "l"(addr),
                         "f"(br[4 * q + 0] * wg), "f"(br[4 * q + 1] * wg),
                         "f"(br[4 * q + 2] * wg), "f"(br[4 * q + 3] * wg));
        } else {
            asm volatile("red.global.add.f32 [%0], %1;" ::
                         "l"(addr), "f"(br[16] * wg));
        }
    }

    float* outw = out_pe + (size_t)(blockIdx.x * 256 + wb) * NC;
    #pragma unroll
    for (int j = 0; j < NC; j++) {
        const int idx = j * 32 + lane;
        const int e   = idx / NC;
        const int c   = idx - e * NC;
        outw[idx] = myBase[e * B_PAD + c];
    }
}

// ============================================================================
// Kernel C: poss_node = recall / neighbours_sum ; emit recall_node
// ============================================================================
__global__ __launch_bounds__(256) void final_kernel(
    const float* __restrict__ ns, float* __restrict__ out_pn,
    float* __restrict__ out_rn)
{
    const int i = blockIdx.x * 256 + threadIdx.x;
    if (i >= N_NODES * NC) return;
    const int n = i / NC, c = i - n * NC;
    const float r = g_recall[n * R_STRIDE + c];
    out_rn[i] = r;
    out_pn[i] = r / ns[n];
}

// ============================================================================
// Kernels Z1/Z2: zero g_recall (split in two so edge_kernel is launch #4,
// which is the launch ncu captures). Stream-ordered before edge's REDs.
// ============================================================================
__global__ __launch_bounds__(256) void zero_lo_kernel()
{
    float4* p = (float4*)g_recall;
    const int half = N_NODES * R_STRIDE / 8;     // 250,000 float4
    for (int i = blockIdx.x * 256 + threadIdx.x; i < half; i += gridDim.x * 256)
        p[i] = make_float4(0.f, 0.f, 0.f, 0.f);
}
__global__ __launch_bounds__(256) void zero_hi_kernel()
{
    float4* p = (float4*)g_recall + N_NODES * R_STRIDE / 8;
    const int half = N_NODES * R_STRIDE / 8;
    for (int i = blockIdx.x * 256 + threadIdx.x; i < half; i += gridDim.x * 256)
        p[i] = make_float4(0.f, 0.f, 0.f, 0.f);
}

// ============================================================================
extern "C" void kernel_launch(void* const* d_in, const int* in_sizes, int n_in,
                              void* d_out, int out_size)
{
    const void *p_feat = nullptr, *p_edges = nullptr, *p_w = nullptr,
               *p_ns = nullptr, *p_We = nullptr, *p_be = nullptr,
               *p_Wt = nullptr, *p_bt = nullptr;
    for (int i = 0; i < n_in; i++) {
        switch (in_sizes[i]) {
            case N_NODES * FEAT_DIM:      p_feat  = d_in[i]; break;
            case N_EDGES * 2:             p_edges = d_in[i]; break;
            case N_EDGES:                 p_w     = d_in[i]; break;
            case N_NODES:                 p_ns    = d_in[i]; break;
            case FEAT_DIM * EMBED_DIM:    p_We    = d_in[i]; break;
            case EMBED_DIM:               p_be    = d_in[i]; break;
            case 2 * EMBED_DIM * NC:      p_Wt    = d_in[i]; break;
            case NC:                      p_bt    = d_in[i]; break;
            default: break;
        }
    }

    const float* feat    = (const float*)p_feat;
    const int2*  edges   = (const int2*)p_edges;
    const float* weights = (const float*)p_w;
    const float* ns      = (const float*)p_ns;
    const float* Wemb    = (const float*)p_We;
    const float* bemb    = (const float*)p_be;
    const float* Wtr     = (const float*)p_Wt;
    const float* btr     = (const float*)p_bt;

    float* out    = (float*)d_out;
    float* out_pn = out;
    float* out_pe = out + (size_t)N_NODES * NC;
    float* out_rn = out + (size_t)N_NODES * NC + (size_t)N_EDGES * NC;

    // Launch order: node(1) zero_lo(2) zero_hi(3) edge(4)<-ncu final(5)
    node_kernel<<<(N_NODES + 255) / 256, 256>>>(feat, Wemb, bemb, Wtr);
    zero_lo_kernel<<<148, 256>>>();
    zero_hi_kernel<<<148, 256>>>();
    edge_kernel<<<N_EDGES / 256, 256>>>(edges, weights, Wtr, btr, out_pe);
    final_kernel<<<(N_NODES * NC + 255) / 256, 256>>>(ns, out_pn, out_rn);
}